// round 14
// baseline (speedup 1.0000x reference)
#include <cuda_runtime.h>
#include <math.h>

#define BC 48          // 16 batch * 3 channels
#define WS 11

typedef unsigned long long u64;

// ---- compile-time gaussian window (sigma=1.5, 11 taps, normalized) ---------
#define GW { 0.00102859f, 0.00759871f, 0.03600077f, 0.10936069f, 0.21300553f, \
             0.26601142f, 0.21300553f, 0.10936069f, 0.03600077f, 0.00759871f, \
             0.00102859f }

// ---------------- f32x2 packed-math helpers (sm_103a) ------------------------
__device__ __forceinline__ u64 pk2(float lo, float hi) {
    u64 r; asm("mov.b64 %0,{%1,%2};" : "=l"(r) : "f"(lo), "f"(hi)); return r;
}
__device__ __forceinline__ void up2(u64 v, float& a, float& b) {
    asm("mov.b64 {%0,%1},%2;" : "=f"(a), "=f"(b) : "l"(v));
}
__device__ __forceinline__ u64 fma2(u64 a, u64 b, u64 c) {
    u64 d; asm("fma.rn.f32x2 %0,%1,%2,%3;" : "=l"(d) : "l"(a), "l"(b), "l"(c)); return d;
}
__device__ __forceinline__ u64 mul2(u64 a, u64 b) {
    u64 d; asm("mul.rn.f32x2 %0,%1,%2;" : "=l"(d) : "l"(a), "l"(b)); return d;
}

// ---------------- device globals (scratch; no runtime allocation) -----------
__device__ double g_cs[5];      // zero-init; self-cleaned by final block
__device__ double g_ss[5];
__device__ int    g_tick;       // zero-init; self-cleaned
__device__ float g_xa[BC * 256 * 256];
__device__ float g_ya[BC * 256 * 256];
__device__ float g_xb[BC * 128 * 128];
__device__ float g_yb[BC * 128 * 128];

// ---- smem layout helpers (dynamic shared) -----------------------------------
__host__ __device__ constexpr int tih_of(int TH)  { return TH + 10; }
__host__ __device__ constexpr int tiw4_of(int TW) { return ((TW + 10) + 3) & ~3; }
__host__ __device__ constexpr int pin_of(int TW)  { return (tiw4_of(TW) + 1) | 1; }
__host__ __device__ constexpr int ph_of(int TW)   { return TW + 1; }
__host__ __device__ constexpr int smem_of(int TW, int TH) {
    return tih_of(TH) * ph_of(TW) * 16 + tih_of(TH) * pin_of(TW) * 8;
}

// ---------------- fused: separable conv + SSIM stats + 2x2 pool -------------
// Rotated basis u=x+y, v=x-y. Filter only packed (u,v) and (u^2,v^2).
// A=filt(u),B=filt(v),Qa=filt(u2),Qb=filt(v2); da=Qa-A^2, db=Qb-B^2:
//   2*s12+C2 = (da-db)/2+C2,  s1+s2+C2 = (da+db)/2+C2
//   2*mu1*mu2+C1 = (A^2-B^2)/2+C1,  mu1^2+mu2^2+C1 = (A^2+B^2)/2+C1
template<int TW, int TH, int NT, int HCW, bool FINAL>
__global__ __launch_bounds__(NT) void ssim_kernel(
    const float* __restrict__ X, const float* __restrict__ Y,
    float* __restrict__ XP, float* __restrict__ YP,
    int H, int W, int level, int do_pool, float* __restrict__ out)
{
    constexpr int TIH = TH + 10, TIW = TW + 10;
    constexpr int TIW4 = tiw4_of(TW);
    constexpr int PIN  = pin_of(TW);      // input pitch (float2 units), odd
    constexpr int PH   = ph_of(TW);       // h-array pitch (float4 units), odd
    constexpr int CG   = TW / HCW;        // h-pass column groups per row
    constexpr int RPT  = (TH * TW) / NT;  // output rows per thread in v-pass
    constexpr int NW   = NT / 32;

    extern __shared__ char dsm[];
    float4* hm   = (float4*)dsm;                     // TIH*PH  (Gu,Gv,Gu2,Gv2)
    float2* s_in = (float2*)(dsm + TIH * PH * 16);   // TIH*PIN (u,v)
    __shared__ double red0[NW], red1[NW];

    const int tid = threadIdx.x;
    const float wreg[WS] = GW;
    u64 wpk[WS];
    #pragma unroll
    for (int k = 0; k < WS; k++) wpk[k] = pk2(wreg[k], wreg[k]);

    const int img  = blockIdx.z;
    const float* Xi = X + (size_t)img * H * W;
    const float* Yi = Y + (size_t)img * H * W;
    const int row0 = blockIdx.y * TH;
    const int col0 = blockIdx.x * TW;

    // ---- load input tile, rotate to (u,v) = (x+y, x-y) ----
    if (row0 + TIH <= H && col0 + TIW4 <= W) {
        constexpr int NCH = TIW4 / 4;     // float4 chunks per row
        for (int i = tid; i < TIH * NCH; i += NT) {
            int r = i / NCH, c4 = (i % NCH) * 4;
            const float4 xv = *(const float4*)&Xi[(size_t)(row0 + r) * W + col0 + c4];
            const float4 yv = *(const float4*)&Yi[(size_t)(row0 + r) * W + col0 + c4];
            float2* dst = &s_in[r * PIN + c4];
            dst[0] = make_float2(xv.x + yv.x, xv.x - yv.x);
            dst[1] = make_float2(xv.y + yv.y, xv.y - yv.y);
            dst[2] = make_float2(xv.z + yv.z, xv.z - yv.z);
            dst[3] = make_float2(xv.w + yv.w, xv.w - yv.w);
        }
    } else {
        for (int i = tid; i < TIH * TIW; i += NT) {
            int r = i / TIW, c = i % TIW;
            int gr = row0 + r, gc = col0 + c;
            float xv = 0.f, yv = 0.f;
            if (gr < H && gc < W) {
                xv = Xi[(size_t)gr * W + gc];
                yv = Yi[(size_t)gr * W + gc];
            }
            s_in[r * PIN + c] = make_float2(xv + yv, xv - yv);
        }
    }
    __syncthreads();

    // ---- fused 2x2 avg pool: x=(u+v)/2, y=(u-v)/2 -> xp=(Su+Sv)/8 ----
    if (do_pool) {
        constexpr int PW = TW / 2, PHT = TH / 2;
        int Ho = H >> 1, Wo = W >> 1;
        for (int i = tid; i < PW * PHT; i += NT) {
            int pr = i / PW, pc = i % PW;
            float2 a = s_in[(2 * pr) * PIN + 2 * pc];
            float2 b = s_in[(2 * pr) * PIN + 2 * pc + 1];
            float2 c2 = s_in[(2 * pr + 1) * PIN + 2 * pc];
            float2 d = s_in[(2 * pr + 1) * PIN + 2 * pc + 1];
            float su = a.x + b.x + c2.x + d.x;
            float sv = a.y + b.y + c2.y + d.y;
            size_t o = (size_t)img * Ho * Wo + (size_t)((row0 >> 1) + pr) * Wo + (col0 >> 1) + pc;
            XP[o] = 0.125f * (su + sv);
            YP[o] = 0.125f * (su - sv);
        }
    }

    // ---- horizontal pass: HCW-column units, row-fastest (conflict-free) ----
    for (int u = tid; u < TIH * CG; u += NT) {
        int cgi = u / TIH;
        int r   = u - cgi * TIH;
        int cg  = cgi * HCW;
        const float2* prow = &s_in[r * PIN + cg];
        u64 m1[HCW], m2[HCW];
        #pragma unroll
        for (int j = 0; j < HCW; j++) { m1[j] = 0; m2[j] = 0; }
        #pragma unroll
        for (int i = 0; i < HCW + 10; i++) {
            float2 v = prow[i];
            u64 vp = pk2(v.x, v.y);
            u64 q  = mul2(vp, vp);
            #pragma unroll
            for (int j = 0; j < HCW; j++) {
                int t = i - j;
                if (t >= 0 && t < WS) {
                    m1[j] = fma2(wpk[t], vp, m1[j]);
                    m2[j] = fma2(wpk[t], q,  m2[j]);
                }
            }
        }
        int o = r * PH + cg;
        #pragma unroll
        for (int j = 0; j < HCW; j++) {
            float a, b, c, d;
            up2(m1[j], a, b);
            up2(m2[j], c, d);
            hm[o + j] = make_float4(a, b, c, d);
        }
    }
    __syncthreads();

    // ---- vertical pass + SSIM math (RPT rows per thread) ----
    const float C1 = 0.01f * 0.01f;
    const float C2 = 0.03f * 0.03f;
    const int c  = tid % TW;
    const int r0 = (tid / TW) * RPT;
    const int Hout = H - 10, Wout = W - 10;
    const bool colok = (col0 + c) < Wout;

    u64 a1[RPT], a2[RPT];
    #pragma unroll
    for (int j = 0; j < RPT; j++) { a1[j] = 0; a2[j] = 0; }

    const float4* pv = &hm[r0 * PH + c];
    #pragma unroll
    for (int k = 0; k < RPT + 10; k++) {
        float4 v = pv[k * PH];
        u64 p1 = pk2(v.x, v.y);
        u64 p2 = pk2(v.z, v.w);
        #pragma unroll
        for (int j = 0; j < RPT; j++) {
            int t = k - j;
            if (t >= 0 && t < WS) {
                a1[j] = fma2(wpk[t], p1, a1[j]);
                a2[j] = fma2(wpk[t], p2, a2[j]);
            }
        }
    }

    float cs_sum = 0.f, ss_sum = 0.f;
    #pragma unroll
    for (int j = 0; j < RPT; j++) {
        if (colok && (row0 + r0 + j) < Hout) {
            u64 sq = mul2(a1[j], a1[j]);     // (A^2, B^2)
            float A2, B2, Qa, Qb;
            up2(sq, A2, B2);
            up2(a2[j], Qa, Qb);
            float da = Qa - A2;
            float db = Qb - B2;
            float num  = 0.5f * (da - db) + C2;
            float den  = 0.5f * (da + db) + C2;
            float lnum = 0.5f * (A2 - B2) + C1;
            float lden = 0.5f * (A2 + B2) + C1;
            cs_sum += __fdividef(num, den);
            ss_sum += __fdividef(lnum * num, lden * den);
        }
    }

    // warp + block reduction
    #pragma unroll
    for (int o = 16; o > 0; o >>= 1) {
        cs_sum += __shfl_down_sync(0xffffffffu, cs_sum, o);
        ss_sum += __shfl_down_sync(0xffffffffu, ss_sum, o);
    }
    if ((tid & 31) == 0) { red0[tid >> 5] = cs_sum; red1[tid >> 5] = ss_sum; }
    __syncthreads();
    if (tid == 0) {
        double a = 0.0, b = 0.0;
        #pragma unroll
        for (int w = 0; w < NW; w++) { a += red0[w]; b += red1[w]; }
        atomicAdd(&g_cs[level], a);
        atomicAdd(&g_ss[level], b);

        if (FINAL) {
            __threadfence();
            int nblk = gridDim.x * gridDim.y * gridDim.z;
            int t = atomicAdd(&g_tick, 1);
            if (t == nblk - 1) {
                __threadfence();
                const double w[5] = {0.0448, 0.2856, 0.3001, 0.2363, 0.1333};
                double ms = 1.0;
                #pragma unroll
                for (int l = 0; l < 5; l++) {
                    int Hl = 512 >> l;
                    double n  = 48.0 * (double)(Hl - 10) * (double)(Hl - 10);
                    double cs = g_cs[l] / n; if (cs < 0.0) cs = 0.0; cs = (cs + 1.0) * 0.5;
                    double ss = g_ss[l] / n; if (ss < 0.0) ss = 0.0; ss = (ss + 1.0) * 0.5;
                    double v  = (l < 4) ? cs : ss;
                    ms *= pow(v, w[l]);
                }
                out[0] = (float)(1.0 - ms);
                // self-clean for next graph replay
                #pragma unroll
                for (int l = 0; l < 5; l++) { g_cs[l] = 0.0; g_ss[l] = 0.0; }
                g_tick = 0;
            }
        }
    }
}

// ---------------- host launch -------------------------------------------------
static inline dim3 conv_grid(int H, int W, int tw, int th) {
    int Hout = H - 10, Wout = W - 10;
    return dim3((Wout + tw - 1) / tw, (Hout + th - 1) / th, BC);
}

extern "C" void kernel_launch(void* const* d_in, const int* in_sizes, int n_in,
                              void* d_out, int out_size)
{
    const float* X0 = (const float*)d_in[0];
    const float* Y0 = (const float*)d_in[1];
    float* out = (float*)d_out;

    float *xa, *ya, *xb, *yb;
    cudaGetSymbolAddress((void**)&xa, g_xa);
    cudaGetSymbolAddress((void**)&ya, g_ya);
    cudaGetSymbolAddress((void**)&xb, g_xb);
    cudaGetSymbolAddress((void**)&yb, g_yb);

    constexpr int SM_TALL  = smem_of(32, 64);   // ~64 KB, 3 blocks/SM
    constexpr int SM_STD   = smem_of(32, 32);   // ~37 KB, 6 blocks/SM
    constexpr int SM_SMALL = smem_of(16, 16);   // ~13 KB

    cudaFuncSetAttribute((const void*)ssim_kernel<32, 64, 256, 4, false>,
                         cudaFuncAttributeMaxDynamicSharedMemorySize, SM_TALL);
    cudaFuncSetAttribute((const void*)ssim_kernel<32, 32, 256, 4, false>,
                         cudaFuncAttributeMaxDynamicSharedMemorySize, SM_STD);
    cudaFuncSetAttribute((const void*)ssim_kernel<16, 16, 256, 4, false>,
                         cudaFuncAttributeMaxDynamicSharedMemorySize, SM_SMALL);
    cudaFuncSetAttribute((const void*)ssim_kernel<16, 16, 256, 4, true>,
                         cudaFuncAttributeMaxDynamicSharedMemorySize, SM_SMALL);

    // level 0: 512 -> pool into xa/ya (256)   (tall 32x64 tiles, RPT=8)
    ssim_kernel<32, 64, 256, 4, false><<<conv_grid(512, 512, 32, 64), 256, SM_TALL>>>(
        X0, Y0, xa, ya, 512, 512, 0, 1, nullptr);
    // level 1: 256 -> pool into xb/yb (128)
    ssim_kernel<32, 64, 256, 4, false><<<conv_grid(256, 256, 32, 64), 256, SM_TALL>>>(
        xa, ya, xb, yb, 256, 256, 1, 1, nullptr);
    // level 2: 128 -> pool into xa/ya (64)    (proven 32x32)
    ssim_kernel<32, 32, 256, 4, false><<<conv_grid(128, 128, 32, 32), 256, SM_STD>>>(
        xb, yb, xa, ya, 128, 128, 2, 1, nullptr);
    // level 3: 64 -> pool into xb/yb (32)
    ssim_kernel<16, 16, 256, 4, false><<<conv_grid(64, 64, 16, 16), 256, SM_SMALL>>>(
        xa, ya, xb, yb, 64, 64, 3, 1, nullptr);
    // level 4: 32, no pool; last block computes final combine + self-clean
    ssim_kernel<16, 16, 256, 4, true><<<conv_grid(32, 32, 16, 16), 256, SM_SMALL>>>(
        xb, yb, nullptr, nullptr, 32, 32, 4, 0, out);
}

// round 15
// speedup vs baseline: 1.1495x; 1.1495x over previous
#include <cuda_runtime.h>
#include <math.h>

#define BC 48          // 16 batch * 3 channels
#define WS 11

typedef unsigned long long u64;

// ---- compile-time gaussian window (sigma=1.5, 11 taps, normalized) ---------
#define GW { 0.00102859f, 0.00759871f, 0.03600077f, 0.10936069f, 0.21300553f, \
             0.26601142f, 0.21300553f, 0.10936069f, 0.03600077f, 0.00759871f, \
             0.00102859f }

// ---------------- f32x2 packed-math helpers (sm_103a) ------------------------
__device__ __forceinline__ u64 pk2(float lo, float hi) {
    u64 r; asm("mov.b64 %0,{%1,%2};" : "=l"(r) : "f"(lo), "f"(hi)); return r;
}
__device__ __forceinline__ void up2(u64 v, float& a, float& b) {
    asm("mov.b64 {%0,%1},%2;" : "=f"(a), "=f"(b) : "l"(v));
}
__device__ __forceinline__ u64 fma2(u64 a, u64 b, u64 c) {
    u64 d; asm("fma.rn.f32x2 %0,%1,%2,%3;" : "=l"(d) : "l"(a), "l"(b), "l"(c)); return d;
}
__device__ __forceinline__ u64 mul2(u64 a, u64 b) {
    u64 d; asm("mul.rn.f32x2 %0,%1,%2;" : "=l"(d) : "l"(a), "l"(b)); return d;
}

// ---------------- device globals (scratch; no runtime allocation) -----------
__device__ double g_cs[5];      // zero-init; self-cleaned by final block
__device__ double g_ss[5];
__device__ int    g_tick;       // zero-init; self-cleaned
__device__ float g_xa[BC * 256 * 256];
__device__ float g_ya[BC * 256 * 256];
__device__ float g_xb[BC * 128 * 128];
__device__ float g_yb[BC * 128 * 128];

// ---------------- fused: separable conv + SSIM stats + 2x2 pool -------------
// Rotated basis u=x+y, v=x-y. Filter only packed (u,v) and (u^2,v^2).
// A=filt(u),B=filt(v),Qa=filt(u2),Qb=filt(v2); da=Qa-A^2, db=Qb-B^2:
//   2*s12+C2 = (da-db)/2+C2,  s1+s2+C2 = (da+db)/2+C2
//   2*mu1*mu2+C1 = (A^2-B^2)/2+C1,  mu1^2+mu2^2+C1 = (A^2+B^2)/2+C1
// FINAL: last finishing block computes the MS-SSIM combine, writes out[0],
// and resets all accumulators (self-cleaning for graph replay).
template<int TW, int TH, int NT, int HCW, bool FINAL>
__global__ __launch_bounds__(NT) void ssim_kernel(
    const float* __restrict__ X, const float* __restrict__ Y,
    float* __restrict__ XP, float* __restrict__ YP,
    int H, int W, int level, int do_pool, float* __restrict__ out)
{
    constexpr int TIH = TH + 10, TIW = TW + 10;
    constexpr int TIW4 = (TIW + 3) & ~3;  // TIW rounded up to float4 multiple
    constexpr int PIN  = (TIW4 + 1) | 1;  // input pitch (float2 units), odd
    constexpr int PH   = TW + 1;          // h-array pitch (float4 units), odd
    constexpr int CG   = TW / HCW;        // h-pass column groups per row
    constexpr int RPT  = (TH * TW) / NT;  // output rows per thread in v-pass
    constexpr int NW   = NT / 32;
    constexpr int NCH  = TIW4 / 4;        // float4 chunks per row

    __shared__ float2 s_in[TIH * PIN];    // packed (u,v)
    __shared__ float4 hm  [TIH * PH];     // (Gu,Gv,Gu2,Gv2)
    __shared__ double red0[NW], red1[NW];

    const int tid = threadIdx.x;
    const float wreg[WS] = GW;
    u64 wpk[WS];
    #pragma unroll
    for (int k = 0; k < WS; k++) wpk[k] = pk2(wreg[k], wreg[k]);

    const int img  = blockIdx.z;
    const float* Xi = X + (size_t)img * H * W;
    const float* Yi = Y + (size_t)img * H * W;
    const int row0 = blockIdx.y * TH;
    const int col0 = blockIdx.x * TW;

    // ---- load input tile, rotate to (u,v) = (x+y, x-y) ----
    if (row0 + TIH <= H && col0 + TIW4 <= W) {
        // interior fast path
        for (int i = tid; i < TIH * NCH; i += NT) {
            int r = i / NCH, c4 = (i % NCH) * 4;
            const float4 xv = *(const float4*)&Xi[(size_t)(row0 + r) * W + col0 + c4];
            const float4 yv = *(const float4*)&Yi[(size_t)(row0 + r) * W + col0 + c4];
            float2* dst = &s_in[r * PIN + c4];
            dst[0] = make_float2(xv.x + yv.x, xv.x - yv.x);
            dst[1] = make_float2(xv.y + yv.y, xv.y - yv.y);
            dst[2] = make_float2(xv.z + yv.z, xv.z - yv.z);
            dst[3] = make_float2(xv.w + yv.w, xv.w - yv.w);
        }
    } else {
        // border path: vectorize the fully in-bounds chunks, guard the rest
        int full_ch = (W - col0) >> 2;            // chunks with all 4 cols in W
        if (full_ch > NCH) full_ch = NCH;
        if (full_ch < 0)   full_ch = 0;
        for (int i = tid; i < TIH * NCH; i += NT) {
            int r = i / NCH, ch = i % NCH;
            int gr = row0 + r, c4 = ch * 4;
            float4 xv = make_float4(0.f, 0.f, 0.f, 0.f);
            float4 yv = make_float4(0.f, 0.f, 0.f, 0.f);
            if (gr < H) {
                if (ch < full_ch) {
                    xv = *(const float4*)&Xi[(size_t)gr * W + col0 + c4];
                    yv = *(const float4*)&Yi[(size_t)gr * W + col0 + c4];
                } else {
                    int base = col0 + c4;
                    const float* xr = &Xi[(size_t)gr * W];
                    const float* yr = &Yi[(size_t)gr * W];
                    if (base     < W) { xv.x = xr[base];     yv.x = yr[base]; }
                    if (base + 1 < W) { xv.y = xr[base + 1]; yv.y = yr[base + 1]; }
                    if (base + 2 < W) { xv.z = xr[base + 2]; yv.z = yr[base + 2]; }
                    if (base + 3 < W) { xv.w = xr[base + 3]; yv.w = yr[base + 3]; }
                }
            }
            float2* dst = &s_in[r * PIN + c4];
            dst[0] = make_float2(xv.x + yv.x, xv.x - yv.x);
            dst[1] = make_float2(xv.y + yv.y, xv.y - yv.y);
            dst[2] = make_float2(xv.z + yv.z, xv.z - yv.z);
            dst[3] = make_float2(xv.w + yv.w, xv.w - yv.w);
        }
    }
    __syncthreads();

    // ---- fused 2x2 avg pool: xp=(Su+Sv)/8, yp=(Su-Sv)/8 ----
    if (do_pool) {
        int Ho = H >> 1, Wo = W >> 1;
        if (TW == 32 && NT == 256) {
            // conflict-free: lane l reads column l, shfl_xor(1) for partner col
            int w = tid >> 5, l = tid & 31;
            #pragma unroll
            for (int it = 0; it < 2; it++) {
                int pr = w + it * 8;              // pooled row 0..15
                float2 a = s_in[(2 * pr) * PIN + l];
                float2 b = s_in[(2 * pr + 1) * PIN + l];
                float su = a.x + b.x;
                float sv = a.y + b.y;
                su += __shfl_xor_sync(0xffffffffu, su, 1);
                sv += __shfl_xor_sync(0xffffffffu, sv, 1);
                if ((l & 1) == 0) {
                    int pc = l >> 1;
                    size_t o = (size_t)img * Ho * Wo
                             + (size_t)((row0 >> 1) + pr) * Wo + (col0 >> 1) + pc;
                    XP[o] = 0.125f * (su + sv);
                    YP[o] = 0.125f * (su - sv);
                }
            }
        } else {
            constexpr int PW = TW / 2, PHT = TH / 2;
            for (int i = tid; i < PW * PHT; i += NT) {
                int pr = i / PW, pc = i % PW;
                float2 a = s_in[(2 * pr) * PIN + 2 * pc];
                float2 b = s_in[(2 * pr) * PIN + 2 * pc + 1];
                float2 c2 = s_in[(2 * pr + 1) * PIN + 2 * pc];
                float2 d = s_in[(2 * pr + 1) * PIN + 2 * pc + 1];
                float su = a.x + b.x + c2.x + d.x;
                float sv = a.y + b.y + c2.y + d.y;
                size_t o = (size_t)img * Ho * Wo
                         + (size_t)((row0 >> 1) + pr) * Wo + (col0 >> 1) + pc;
                XP[o] = 0.125f * (su + sv);
                YP[o] = 0.125f * (su - sv);
            }
        }
    }

    // ---- horizontal pass: HCW-column units, row-fastest (conflict-free) ----
    for (int u = tid; u < TIH * CG; u += NT) {
        int cgi = u / TIH;
        int r   = u - cgi * TIH;
        int cg  = cgi * HCW;
        const float2* prow = &s_in[r * PIN + cg];
        u64 m1[HCW], m2[HCW];
        #pragma unroll
        for (int j = 0; j < HCW; j++) { m1[j] = 0; m2[j] = 0; }
        #pragma unroll
        for (int i = 0; i < HCW + 10; i++) {
            float2 v = prow[i];
            u64 vp = pk2(v.x, v.y);
            u64 q  = mul2(vp, vp);
            #pragma unroll
            for (int j = 0; j < HCW; j++) {
                int t = i - j;
                if (t >= 0 && t < WS) {
                    m1[j] = fma2(wpk[t], vp, m1[j]);
                    m2[j] = fma2(wpk[t], q,  m2[j]);
                }
            }
        }
        int o = r * PH + cg;
        #pragma unroll
        for (int j = 0; j < HCW; j++) {
            float a, b, c, d;
            up2(m1[j], a, b);
            up2(m2[j], c, d);
            hm[o + j] = make_float4(a, b, c, d);
        }
    }
    __syncthreads();

    // ---- vertical pass + SSIM math (RPT rows per thread) ----
    const float C1 = 0.01f * 0.01f;
    const float C2 = 0.03f * 0.03f;
    const int c  = tid % TW;
    const int r0 = (tid / TW) * RPT;
    const int Hout = H - 10, Wout = W - 10;
    const bool colok = (col0 + c) < Wout;

    u64 a1[RPT], a2[RPT];
    #pragma unroll
    for (int j = 0; j < RPT; j++) { a1[j] = 0; a2[j] = 0; }

    const float4* pv = &hm[r0 * PH + c];
    #pragma unroll
    for (int k = 0; k < RPT + 10; k++) {
        float4 v = pv[k * PH];
        u64 p1 = pk2(v.x, v.y);
        u64 p2 = pk2(v.z, v.w);
        #pragma unroll
        for (int j = 0; j < RPT; j++) {
            int t = k - j;
            if (t >= 0 && t < WS) {
                a1[j] = fma2(wpk[t], p1, a1[j]);
                a2[j] = fma2(wpk[t], p2, a2[j]);
            }
        }
    }

    float cs_sum = 0.f, ss_sum = 0.f;
    #pragma unroll
    for (int j = 0; j < RPT; j++) {
        if (colok && (row0 + r0 + j) < Hout) {
            u64 sq = mul2(a1[j], a1[j]);     // (A^2, B^2)
            float A2, B2, Qa, Qb;
            up2(sq, A2, B2);
            up2(a2[j], Qa, Qb);
            float da = Qa - A2;
            float db = Qb - B2;
            float num  = 0.5f * (da - db) + C2;
            float den  = 0.5f * (da + db) + C2;
            float lnum = 0.5f * (A2 - B2) + C1;
            float lden = 0.5f * (A2 + B2) + C1;
            cs_sum += __fdividef(num, den);
            ss_sum += __fdividef(lnum * num, lden * den);
        }
    }

    // warp + block reduction
    #pragma unroll
    for (int o = 16; o > 0; o >>= 1) {
        cs_sum += __shfl_down_sync(0xffffffffu, cs_sum, o);
        ss_sum += __shfl_down_sync(0xffffffffu, ss_sum, o);
    }
    if ((tid & 31) == 0) { red0[tid >> 5] = cs_sum; red1[tid >> 5] = ss_sum; }
    __syncthreads();
    if (tid == 0) {
        double a = 0.0, b = 0.0;
        #pragma unroll
        for (int w = 0; w < NW; w++) { a += red0[w]; b += red1[w]; }
        atomicAdd(&g_cs[level], a);
        atomicAdd(&g_ss[level], b);

        if (FINAL) {
            __threadfence();
            int nblk = gridDim.x * gridDim.y * gridDim.z;
            int t = atomicAdd(&g_tick, 1);
            if (t == nblk - 1) {
                __threadfence();
                const double w[5] = {0.0448, 0.2856, 0.3001, 0.2363, 0.1333};
                double ms = 1.0;
                #pragma unroll
                for (int l = 0; l < 5; l++) {
                    int Hl = 512 >> l;
                    double n  = 48.0 * (double)(Hl - 10) * (double)(Hl - 10);
                    double cs = g_cs[l] / n; if (cs < 0.0) cs = 0.0; cs = (cs + 1.0) * 0.5;
                    double ss = g_ss[l] / n; if (ss < 0.0) ss = 0.0; ss = (ss + 1.0) * 0.5;
                    double v  = (l < 4) ? cs : ss;
                    ms *= pow(v, w[l]);
                }
                out[0] = (float)(1.0 - ms);
                // self-clean for next graph replay
                #pragma unroll
                for (int l = 0; l < 5; l++) { g_cs[l] = 0.0; g_ss[l] = 0.0; }
                g_tick = 0;
            }
        }
    }
}

// ---------------- host launch -------------------------------------------------
static inline dim3 conv_grid(int H, int W, int tw, int th) {
    int Hout = H - 10, Wout = W - 10;
    return dim3((Wout + tw - 1) / tw, (Hout + th - 1) / th, BC);
}

extern "C" void kernel_launch(void* const* d_in, const int* in_sizes, int n_in,
                              void* d_out, int out_size)
{
    const float* X0 = (const float*)d_in[0];
    const float* Y0 = (const float*)d_in[1];
    float* out = (float*)d_out;

    float *xa, *ya, *xb, *yb;
    cudaGetSymbolAddress((void**)&xa, g_xa);
    cudaGetSymbolAddress((void**)&ya, g_ya);
    cudaGetSymbolAddress((void**)&xb, g_xb);
    cudaGetSymbolAddress((void**)&yb, g_yb);

    // level 0: 512 -> pool into xa/ya (256)
    ssim_kernel<32, 32, 256, 4, false><<<conv_grid(512, 512, 32, 32), 256>>>(
        X0, Y0, xa, ya, 512, 512, 0, 1, nullptr);
    // level 1: 256 -> pool into xb/yb (128)
    ssim_kernel<32, 32, 256, 4, false><<<conv_grid(256, 256, 32, 32), 256>>>(
        xa, ya, xb, yb, 256, 256, 1, 1, nullptr);
    // level 2: 128 -> pool into xa/ya (64)
    ssim_kernel<32, 32, 256, 4, false><<<conv_grid(128, 128, 32, 32), 256>>>(
        xb, yb, xa, ya, 128, 128, 2, 1, nullptr);
    // level 3: 64 -> pool into xb/yb (32)
    ssim_kernel<16, 16, 256, 4, false><<<conv_grid(64, 64, 16, 16), 256>>>(
        xa, ya, xb, yb, 64, 64, 3, 1, nullptr);
    // level 4: 32, no pool; last block computes final combine + self-clean
    ssim_kernel<16, 16, 256, 4, true><<<conv_grid(32, 32, 16, 16), 256>>>(
        xb, yb, nullptr, nullptr, 32, 32, 4, 0, out);
}

// round 16
// speedup vs baseline: 1.2027x; 1.0463x over previous
#include <cuda_runtime.h>
#include <math.h>

#define BC 48          // 16 batch * 3 channels
#define WS 11

typedef unsigned long long u64;

// ---- compile-time gaussian window (sigma=1.5, 11 taps, normalized) ---------
#define GW { 0.00102859f, 0.00759871f, 0.03600077f, 0.10936069f, 0.21300553f, \
             0.26601142f, 0.21300553f, 0.10936069f, 0.03600077f, 0.00759871f, \
             0.00102859f }

// ---------------- f32x2 packed-math helpers (sm_103a) ------------------------
__device__ __forceinline__ u64 pk2(float lo, float hi) {
    u64 r; asm("mov.b64 %0,{%1,%2};" : "=l"(r) : "f"(lo), "f"(hi)); return r;
}
__device__ __forceinline__ void up2(u64 v, float& a, float& b) {
    asm("mov.b64 {%0,%1},%2;" : "=f"(a), "=f"(b) : "l"(v));
}
__device__ __forceinline__ u64 fma2(u64 a, u64 b, u64 c) {
    u64 d; asm("fma.rn.f32x2 %0,%1,%2,%3;" : "=l"(d) : "l"(a), "l"(b), "l"(c)); return d;
}
__device__ __forceinline__ u64 mul2(u64 a, u64 b) {
    u64 d; asm("mul.rn.f32x2 %0,%1,%2;" : "=l"(d) : "l"(a), "l"(b)); return d;
}

// ---------------- device globals (scratch; no runtime allocation) -----------
__device__ double g_cs[5];      // zero-init; self-cleaned by final block
__device__ double g_ss[5];
__device__ int    g_tick;       // zero-init; self-cleaned
__device__ float g_xb[BC * 128 * 128];   // pool^2 of inputs (written by L1 tiles)
__device__ float g_yb[BC * 128 * 128];

// tile geometry (the proven 32x32 / 256-thread shape)
#define TTW  32
#define TTH  32
#define TNT  256
#define TIH  42
#define TIW  42
#define TIW4 44
#define PIN  45      // s_in pitch (float2), odd
#define PPH  33      // hm pitch (float4), odd
#define TCG  8       // h-pass column groups (HCW=4)
#define RPT  4
#define NWRP 8
#define NCH  11      // float4 chunks per row (P=0 fast path)

// ---------------- tile core: load(+on-the-fly pool^P) + conv + stats --------
// Rotated basis u=x+y, v=x-y. Filter packed (u,v) and (u^2,v^2).
// P = number of 2x2 pools applied during load (source Hs x Hs -> Hp = Hs>>P).
__device__ __forceinline__ void ssim_tile_core(
    const float* __restrict__ X, const float* __restrict__ Y,
    float* __restrict__ XP, float* __restrict__ YP,
    int Hs, int P, int lvl, int img, int row0, int col0, int do_pool)
{
    __shared__ float2 s_in[TIH * PIN];    // packed (u,v) at pooled resolution
    __shared__ float4 hm  [TIH * PPH];    // (Gu,Gv,Gu2,Gv2)
    __shared__ double red0[NWRP], red1[NWRP];

    const int tid = threadIdx.x;
    const float wreg[WS] = GW;
    u64 wpk[WS];
    #pragma unroll
    for (int k = 0; k < WS; k++) wpk[k] = pk2(wreg[k], wreg[k]);

    const int Hp = Hs >> P;               // pooled (conv input) resolution
    const float* Xi = X + (size_t)img * Hs * Hs;
    const float* Yi = Y + (size_t)img * Hs * Hs;

    // ---- load phase ----
    if (P == 0) {
        if (row0 + TIH <= Hp && col0 + TIW4 <= Hp) {
            for (int i = tid; i < TIH * NCH; i += TNT) {
                int r = i / NCH, c4 = (i % NCH) * 4;
                const float4 xv = *(const float4*)&Xi[(size_t)(row0 + r) * Hs + col0 + c4];
                const float4 yv = *(const float4*)&Yi[(size_t)(row0 + r) * Hs + col0 + c4];
                float2* dst = &s_in[r * PIN + c4];
                dst[0] = make_float2(xv.x + yv.x, xv.x - yv.x);
                dst[1] = make_float2(xv.y + yv.y, xv.y - yv.y);
                dst[2] = make_float2(xv.z + yv.z, xv.z - yv.z);
                dst[3] = make_float2(xv.w + yv.w, xv.w - yv.w);
            }
        } else {
            int full_ch = (Hp - col0) >> 2;
            if (full_ch > NCH) full_ch = NCH;
            if (full_ch < 0)   full_ch = 0;
            for (int i = tid; i < TIH * NCH; i += TNT) {
                int r = i / NCH, ch = i % NCH;
                int gr = row0 + r, c4 = ch * 4;
                float4 xv = make_float4(0.f, 0.f, 0.f, 0.f);
                float4 yv = make_float4(0.f, 0.f, 0.f, 0.f);
                if (gr < Hp) {
                    if (ch < full_ch) {
                        xv = *(const float4*)&Xi[(size_t)gr * Hs + col0 + c4];
                        yv = *(const float4*)&Yi[(size_t)gr * Hs + col0 + c4];
                    } else {
                        int base = col0 + c4;
                        const float* xr = &Xi[(size_t)gr * Hs];
                        const float* yr = &Yi[(size_t)gr * Hs];
                        if (base     < Hp) { xv.x = xr[base];     yv.x = yr[base]; }
                        if (base + 1 < Hp) { xv.y = xr[base + 1]; yv.y = yr[base + 1]; }
                        if (base + 2 < Hp) { xv.z = xr[base + 2]; yv.z = yr[base + 2]; }
                        if (base + 3 < Hp) { xv.w = xr[base + 3]; yv.w = yr[base + 3]; }
                    }
                }
                float2* dst = &s_in[r * PIN + c4];
                dst[0] = make_float2(xv.x + yv.x, xv.x - yv.x);
                dst[1] = make_float2(xv.y + yv.y, xv.y - yv.y);
                dst[2] = make_float2(xv.z + yv.z, xv.z - yv.z);
                dst[3] = make_float2(xv.w + yv.w, xv.w - yv.w);
            }
        }
    } else if (P == 1) {
        // each unit = 2 adjacent pooled cells = 2x4 raw = one float4 per raw row
        if (row0 + TIH <= Hp && col0 + TIW <= Hp) {
            for (int i = tid; i < TIH * 21; i += TNT) {
                int r = i / 21, c0 = (i % 21) * 2;
                int rb = (row0 + r) << 1, cb = (col0 + c0) << 1;
                float4 x0 = *(const float4*)&Xi[(size_t)rb * Hs + cb];
                float4 x1 = *(const float4*)&Xi[(size_t)(rb + 1) * Hs + cb];
                float4 y0 = *(const float4*)&Yi[(size_t)rb * Hs + cb];
                float4 y1 = *(const float4*)&Yi[(size_t)(rb + 1) * Hs + cb];
                float pxa = (x0.x + x0.y + x1.x + x1.y) * 0.25f;
                float pxb = (x0.z + x0.w + x1.z + x1.w) * 0.25f;
                float pya = (y0.x + y0.y + y1.x + y1.y) * 0.25f;
                float pyb = (y0.z + y0.w + y1.z + y1.w) * 0.25f;
                s_in[r * PIN + c0]     = make_float2(pxa + pya, pxa - pya);
                s_in[r * PIN + c0 + 1] = make_float2(pxb + pyb, pxb - pyb);
            }
        } else {
            for (int i = tid; i < TIH * TIW; i += TNT) {
                int r = i / TIW, c = i % TIW;
                int pr = row0 + r, pc = col0 + c;
                float px = 0.f, py = 0.f;
                if (pr < Hp && pc < Hp) {
                    int rb = pr << 1, cb = pc << 1;
                    px = (Xi[(size_t)rb * Hs + cb] + Xi[(size_t)rb * Hs + cb + 1]
                        + Xi[(size_t)(rb + 1) * Hs + cb] + Xi[(size_t)(rb + 1) * Hs + cb + 1]) * 0.25f;
                    py = (Yi[(size_t)rb * Hs + cb] + Yi[(size_t)rb * Hs + cb + 1]
                        + Yi[(size_t)(rb + 1) * Hs + cb] + Yi[(size_t)(rb + 1) * Hs + cb + 1]) * 0.25f;
                }
                s_in[r * PIN + c] = make_float2(px + py, px - py);
            }
        }
    } else {
        // P == 2: each pooled cell = 4x4 raw block (float4 per raw row)
        for (int i = tid; i < TIH * TIW; i += TNT) {
            int r = i / TIW, c = i % TIW;
            int pr = row0 + r, pc = col0 + c;
            float sx = 0.f, sy = 0.f;
            if (pr < Hp && pc < Hp) {
                int rb = pr << 2, cb = pc << 2;
                #pragma unroll
                for (int k2 = 0; k2 < 4; k2++) {
                    float4 xv = *(const float4*)&Xi[(size_t)(rb + k2) * Hs + cb];
                    float4 yv = *(const float4*)&Yi[(size_t)(rb + k2) * Hs + cb];
                    sx += xv.x + xv.y + xv.z + xv.w;
                    sy += yv.x + yv.y + yv.z + yv.w;
                }
                sx *= 0.0625f;
                sy *= 0.0625f;
            }
            s_in[r * PIN + c] = make_float2(sx + sy, sx - sy);
        }
    }
    __syncthreads();

    // ---- pool write (L1 only): conflict-free shfl scheme ----
    if (do_pool) {
        int Ho = Hp >> 1;
        int w = tid >> 5, l = tid & 31;
        #pragma unroll
        for (int it = 0; it < 2; it++) {
            int pr = w + it * 8;
            float2 a = s_in[(2 * pr) * PIN + l];
            float2 b = s_in[(2 * pr + 1) * PIN + l];
            float su = a.x + b.x;
            float sv = a.y + b.y;
            su += __shfl_xor_sync(0xffffffffu, su, 1);
            sv += __shfl_xor_sync(0xffffffffu, sv, 1);
            if ((l & 1) == 0) {
                int pc = l >> 1;
                size_t o = (size_t)img * Ho * Ho
                         + (size_t)((row0 >> 1) + pr) * Ho + (col0 >> 1) + pc;
                XP[o] = 0.125f * (su + sv);
                YP[o] = 0.125f * (su - sv);
            }
        }
    }

    // ---- horizontal pass: 4-column units, row-fastest (conflict-free) ----
    for (int u = tid; u < TIH * TCG; u += TNT) {
        int cgi = u / TIH;
        int r   = u - cgi * TIH;
        int cg  = cgi * 4;
        const float2* prow = &s_in[r * PIN + cg];
        u64 m1[4], m2[4];
        #pragma unroll
        for (int j = 0; j < 4; j++) { m1[j] = 0; m2[j] = 0; }
        #pragma unroll
        for (int i = 0; i < 14; i++) {
            float2 v = prow[i];
            u64 vp = pk2(v.x, v.y);
            u64 q  = mul2(vp, vp);
            #pragma unroll
            for (int j = 0; j < 4; j++) {
                int t = i - j;
                if (t >= 0 && t < WS) {
                    m1[j] = fma2(wpk[t], vp, m1[j]);
                    m2[j] = fma2(wpk[t], q,  m2[j]);
                }
            }
        }
        int o = r * PPH + cg;
        #pragma unroll
        for (int j = 0; j < 4; j++) {
            float a, b, c, d;
            up2(m1[j], a, b);
            up2(m2[j], c, d);
            hm[o + j] = make_float4(a, b, c, d);
        }
    }
    __syncthreads();

    // ---- vertical pass + SSIM math ----
    const float C1 = 0.01f * 0.01f;
    const float C2 = 0.03f * 0.03f;
    const int c  = tid % TTW;
    const int r0 = (tid / TTW) * RPT;
    const int Hout = Hp - 10;
    const bool colok = (col0 + c) < Hout;

    u64 a1[RPT], a2[RPT];
    #pragma unroll
    for (int j = 0; j < RPT; j++) { a1[j] = 0; a2[j] = 0; }

    const float4* pv = &hm[r0 * PPH + c];
    #pragma unroll
    for (int k = 0; k < RPT + 10; k++) {
        float4 v = pv[k * PPH];
        u64 p1 = pk2(v.x, v.y);
        u64 p2 = pk2(v.z, v.w);
        #pragma unroll
        for (int j = 0; j < RPT; j++) {
            int t = k - j;
            if (t >= 0 && t < WS) {
                a1[j] = fma2(wpk[t], p1, a1[j]);
                a2[j] = fma2(wpk[t], p2, a2[j]);
            }
        }
    }

    float cs_sum = 0.f, ss_sum = 0.f;
    #pragma unroll
    for (int j = 0; j < RPT; j++) {
        if (colok && (row0 + r0 + j) < Hout) {
            u64 sq = mul2(a1[j], a1[j]);     // (A^2, B^2)
            float A2, B2, Qa, Qb;
            up2(sq, A2, B2);
            up2(a2[j], Qa, Qb);
            float da = Qa - A2;
            float db = Qb - B2;
            float num  = 0.5f * (da - db) + C2;
            float den  = 0.5f * (da + db) + C2;
            float lnum = 0.5f * (A2 - B2) + C1;
            float lden = 0.5f * (A2 + B2) + C1;
            cs_sum += __fdividef(num, den);
            ss_sum += __fdividef(lnum * num, lden * den);
        }
    }

    #pragma unroll
    for (int o = 16; o > 0; o >>= 1) {
        cs_sum += __shfl_down_sync(0xffffffffu, cs_sum, o);
        ss_sum += __shfl_down_sync(0xffffffffu, ss_sum, o);
    }
    if ((tid & 31) == 0) { red0[tid >> 5] = cs_sum; red1[tid >> 5] = ss_sum; }
    __syncthreads();
    if (tid == 0) {
        double a = 0.0, b = 0.0;
        #pragma unroll
        for (int w = 0; w < NWRP; w++) { a += red0[w]; b += red1[w]; }
        atomicAdd(&g_cs[lvl], a);
        atomicAdd(&g_ss[lvl], b);
    }
}

// ---------------- launch A: levels 0 and 1 concurrently ---------------------
// bx in [0,320): [0,256) -> L0 tiles (read raw, no pool-out),
//                [256,320) -> L1 tiles (read raw with on-the-fly 2x2 pool,
//                             write pool^2 into the 128^2 buffers)
__global__ __launch_bounds__(TNT) void ssim_kA(
    const float* __restrict__ X0, const float* __restrict__ Y0,
    float* __restrict__ XB, float* __restrict__ YB)
{
    int bx = blockIdx.x, img = blockIdx.z;
    int P, lvl, r0, c0, pool;
    if (bx < 256) { P = 0; lvl = 0; r0 = (bx >> 4) * 32; c0 = (bx & 15) * 32; pool = 0; }
    else { int b = bx - 256; P = 1; lvl = 1; r0 = (b >> 3) * 32; c0 = (b & 7) * 32; pool = 1; }
    ssim_tile_core(X0, Y0, XB, YB, 512, P, lvl, img, r0, c0, pool);
}

// ---------------- launch B: levels 2,3,4 concurrently + final combine -------
// bx in [0,21): [0,16) L2 (P=0), [16,20) L3 (P=1), 20 L4 (P=2). All read the
// 128^2 buffers. Last finishing block computes MS-SSIM and self-cleans.
__global__ __launch_bounds__(TNT) void ssim_kB(
    const float* __restrict__ XB, const float* __restrict__ YB,
    float* __restrict__ out)
{
    int bx = blockIdx.x, img = blockIdx.z;
    int P, lvl, r0, c0;
    if (bx < 16)      { P = 0; lvl = 2; r0 = (bx >> 2) * 32; c0 = (bx & 3) * 32; }
    else if (bx < 20) { int b = bx - 16; P = 1; lvl = 3; r0 = (b >> 1) * 32; c0 = (b & 1) * 32; }
    else              { P = 2; lvl = 4; r0 = 0; c0 = 0; }
    ssim_tile_core(XB, YB, nullptr, nullptr, 128, P, lvl, img, r0, c0, 0);

    if (threadIdx.x == 0) {
        __threadfence();
        const int nblk = 21 * BC;
        int t = atomicAdd(&g_tick, 1);
        if (t == nblk - 1) {
            __threadfence();
            const double w[5] = {0.0448, 0.2856, 0.3001, 0.2363, 0.1333};
            double ms = 1.0;
            #pragma unroll
            for (int l = 0; l < 5; l++) {
                int Hl = 512 >> l;
                double n  = 48.0 * (double)(Hl - 10) * (double)(Hl - 10);
                double cs = g_cs[l] / n; if (cs < 0.0) cs = 0.0; cs = (cs + 1.0) * 0.5;
                double ss = g_ss[l] / n; if (ss < 0.0) ss = 0.0; ss = (ss + 1.0) * 0.5;
                double v  = (l < 4) ? cs : ss;
                ms *= pow(v, w[l]);
            }
            out[0] = (float)(1.0 - ms);
            #pragma unroll
            for (int l = 0; l < 5; l++) { g_cs[l] = 0.0; g_ss[l] = 0.0; }
            g_tick = 0;
        }
    }
}

// ---------------- host launch -------------------------------------------------
extern "C" void kernel_launch(void* const* d_in, const int* in_sizes, int n_in,
                              void* d_out, int out_size)
{
    const float* X0 = (const float*)d_in[0];
    const float* Y0 = (const float*)d_in[1];
    float* out = (float*)d_out;

    float *xb, *yb;
    cudaGetSymbolAddress((void**)&xb, g_xb);
    cudaGetSymbolAddress((void**)&yb, g_yb);

    // A: L0 (256 tiles) + L1 (64 tiles) per image, concurrent
    ssim_kA<<<dim3(320, 1, BC), TNT>>>(X0, Y0, xb, yb);
    // B: L2 (16) + L3 (4) + L4 (1) per image, concurrent; final combine inside
    ssim_kB<<<dim3(21, 1, BC), TNT>>>(xb, yb, out);
}